// round 14
// baseline (speedup 1.0000x reference)
#include <cuda_runtime.h>
#include <cuda_bf16.h>
#include <cuda_fp16.h>
#include <math.h>
#include <float.h>

#define N_TOK 32768   // B*T
#define DC    256
#define DIN   512
#define NQCB  8
#define NBINS 1024
#define TAU   6.0f    // screen window (bf16 mma + fp16 value rounding budget)
#define KS    768     // split-K for bf16x3 out-projection

// -------- scratch (device globals: allocation-free) --------
__device__ float g_h[(size_t)N_TOK * DC];
__device__ float g_res[(size_t)N_TOK * DC];
__device__ __nv_bfloat16 g_res16[(size_t)N_TOK * DC];
__device__ __nv_bfloat16 g_cb16[(size_t)NQCB * NBINS * DC];
__device__ uint2 g_part[(size_t)N_TOK * 8];          // per (token, n-tile): {f32 min, count}
__device__ uint4 g_candl[(size_t)N_TOK * 8];         // per (token, n-tile): 4 x {f16 s<<16 | bin}
__device__ __nv_bfloat16 g_qs[(size_t)N_TOK * KS];   // [qh | ql | qh]
__device__ __nv_bfloat16 g_ws[(size_t)DIN * KS];     // [wh | wh | wl]
__device__ float g_r2[N_TOK];
__device__ float g_e2[NQCB * NBINS];
__device__ float g_commit;

__global__ void init_kernel() { g_commit = 0.f; }

// XLA/Eigen float tanh rational approximation (matches reference bits)
__device__ __forceinline__ float tanh_ref(float x) {
    const float kClamp = 7.90531110763549805f;
    float xc = fminf(fmaxf(x, -kClamp), kClamp);
    const float a1  = 4.89352455891786e-03f, a3 = 6.37261928875436e-04f,
                a5  = 1.48572235717979e-05f, a7 = 5.12229709037114e-08f,
                a9  = -8.60467152213735e-11f, a11 = 2.00018790482477e-13f,
                a13 = -2.76076847742355e-16f;
    const float b0 = 4.89352518554385e-03f, b2 = 2.26843463243900e-03f,
                b4 = 1.18534705686654e-04f, b6 = 1.19825839466702e-06f;
    float x2 = __fmul_rn(xc, xc);
    float p = fmaf(x2, a13, a11);
    p = fmaf(x2, p, a9);  p = fmaf(x2, p, a7);
    p = fmaf(x2, p, a5);  p = fmaf(x2, p, a3);
    p = fmaf(x2, p, a1);  p = __fmul_rn(xc, p);
    float q = fmaf(x2, b6, b4);
    q = fmaf(x2, q, b2);  q = fmaf(x2, q, b0);
    float r = __fdiv_rn(p, q);
    return (fabsf(x) < 0.0004f) ? x : r;
}

// ||e||^2 per codebook row, XLA row-reduce order
__global__ void e2_kernel(const float* __restrict__ cb) {
    int gw   = (blockIdx.x * blockDim.x + threadIdx.x) >> 5;
    int lane = threadIdx.x & 31;
    if (gw >= NQCB * NBINS) return;
    const float* row = cb + (size_t)gw * DC;
    float s = 0.f;
    #pragma unroll
    for (int j = 0; j < DC / 32; ++j) {
        float v = row[lane + j * 32];
        s = __fadd_rn(s, __fmul_rn(v, v));
    }
    #pragma unroll
    for (int off = 16; off; off >>= 1)
        s = __fadd_rn(s, __shfl_down_sync(0xffffffffu, s, off));
    if (lane == 0) g_e2[gw] = s;
}

// codebooks fp32 -> bf16
__global__ void cb16_kernel(const float* __restrict__ cb) {
    size_t i = (size_t)blockIdx.x * blockDim.x + threadIdx.x;
    float4 v = ((const float4*)cb)[i];
    __nv_bfloat16 o[4];
    o[0] = __float2bfloat16(v.x); o[1] = __float2bfloat16(v.y);
    o[2] = __float2bfloat16(v.z); o[3] = __float2bfloat16(v.w);
    *(uint2*)(g_cb16 + i * 4) = *(uint2*)o;
}

// out_w split: [wh | wh | wl] rows of KS
__global__ void wsplit_kernel(const float* __restrict__ w) {
    int n = blockIdx.x, k = threadIdx.x;
    float v = w[(size_t)n * DC + k];
    __nv_bfloat16 hi = __float2bfloat16(v);
    __nv_bfloat16 lo = __float2bfloat16(__fsub_rn(v, __bfloat162float(hi)));
    g_ws[(size_t)n * KS + k]           = hi;
    g_ws[(size_t)n * KS + DC + k]      = hi;
    g_ws[(size_t)n * KS + 2 * DC + k]  = lo;
}

// quantized = h - res, split to [qh | ql | qh]
__global__ void qsplit_kernel() {
    int idx = blockIdx.x * blockDim.x + threadIdx.x;
    int m = idx >> 8, k = idx & 255;
    float q = __fsub_rn(g_h[(size_t)m * DC + k], g_res[(size_t)m * DC + k]);
    __nv_bfloat16 hi = __float2bfloat16(q);
    __nv_bfloat16 lo = __float2bfloat16(__fsub_rn(q, __bfloat162float(hi)));
    g_qs[(size_t)m * KS + k]          = hi;
    g_qs[(size_t)m * KS + DC + k]     = lo;
    g_qs[(size_t)m * KS + 2 * DC + k] = hi;
}

// after gemm_in: residual bf16 + r2 (one warp per token)
__global__ void prep_kernel() {
    const int wid = threadIdx.x >> 5, lane = threadIdx.x & 31;
    const int tok = blockIdx.x * 8 + wid;
    const float* r = g_res + (size_t)tok * DC;
    __nv_bfloat16* r16 = g_res16 + (size_t)tok * DC;
    float s = 0.f;
    #pragma unroll
    for (int j = 0; j < 8; ++j) {
        int d = lane + j * 32;
        float v = r[d];
        r16[d] = __float2bfloat16(v);
        s = __fadd_rn(s, __fmul_rn(v, v));
    }
    #pragma unroll
    for (int off = 16; off; off >>= 1)
        s = __fadd_rn(s, __shfl_down_sync(0xffffffffu, s, off));
    if (lane == 0) g_r2[tok] = s;
}

// ---------------- PTX helpers ----------------
__device__ __forceinline__ unsigned int smaddr(const void* p) {
    return (unsigned int)__cvta_generic_to_shared(p);
}
__device__ __forceinline__ void cp16(unsigned int dst, const void* src) {
    asm volatile("cp.async.cg.shared.global [%0], [%1], 16;\n" :: "r"(dst), "l"(src));
}
__device__ __forceinline__ void cp_commit() { asm volatile("cp.async.commit_group;\n"); }
__device__ __forceinline__ void cp_wait0()  { asm volatile("cp.async.wait_group 0;\n"); }
__device__ __forceinline__ void ldmx4(unsigned int& r0, unsigned int& r1,
                                      unsigned int& r2, unsigned int& r3,
                                      unsigned int addr) {
    asm volatile("ldmatrix.sync.aligned.m8n8.x4.shared.b16 {%0,%1,%2,%3}, [%4];\n"
                 : "=r"(r0), "=r"(r1), "=r"(r2), "=r"(r3) : "r"(addr));
}
__device__ __forceinline__ void mma16816(float* d, const unsigned int* a,
                                         unsigned int b0, unsigned int b1) {
    asm volatile("mma.sync.aligned.m16n8k16.row.col.f32.bf16.bf16.f32 "
                 "{%0,%1,%2,%3}, {%4,%5,%6,%7}, {%8,%9}, {%0,%1,%2,%3};\n"
                 : "+f"(d[0]), "+f"(d[1]), "+f"(d[2]), "+f"(d[3])
                 : "r"(a[0]), "r"(a[1]), "r"(a[2]), "r"(a[3]), "r"(b0), "r"(b1));
}

// ---------------------------------------------------------------------------
// SCREEN: scores s = e2 - 2*(bf16(r).bf16(e)) for a 128-token x 128-bin tile.
// Epilogue: CTA-local per-token min + SMEM-atomic candidate lists (cap 4),
// then ONE coalesced global write-out per token. No global atomics, no S.
// ---------------------------------------------------------------------------
__global__ void __launch_bounds__(256, 2) screen_kernel(int t)
{
    __shared__ __align__(16) unsigned short smA[2][128 * 40];
    __shared__ __align__(16) unsigned short smB[2][128 * 40];
    __shared__ float sbest[2][128];
    __shared__ int scnt[128];
    __shared__ __align__(16) unsigned int scand[128][4];
    const int tid   = threadIdx.x;
    const int mBase = blockIdx.y * 128;
    const int nb    = blockIdx.x;          // n-tile 0..7
    const int nBase = nb * 128;
    const int wid = tid >> 5, lane = tid & 31;
    const int wm = wid & 3, wn = wid >> 2;

    const int c0 = tid * 2;
    const int row0 = c0 >> 2, q0 = c0 & 3;
    const int row1 = (c0 + 1) >> 2, q1 = (c0 + 1) & 3;
    const __nv_bfloat16* Ag = g_res16 + (size_t)mBase * DC;
    const __nv_bfloat16* Bg = g_cb16 + (size_t)t * NBINS * DC + (size_t)nBase * DC;
    const float* e2t = g_e2 + t * NBINS;

    if (tid < 128) { sbest[0][tid] = FLT_MAX; sbest[1][tid] = FLT_MAX; scnt[tid] = 0; }

    float acc[2][8][4];
    #pragma unroll
    for (int i = 0; i < 2; ++i)
        #pragma unroll
        for (int j = 0; j < 8; ++j)
            #pragma unroll
            for (int k = 0; k < 4; ++k) acc[i][j][k] = 0.f;

    cp16(smaddr(&smA[0][row0 * 40 + q0 * 8]), Ag + row0 * DC + q0 * 8);
    cp16(smaddr(&smA[0][row1 * 40 + q1 * 8]), Ag + row1 * DC + q1 * 8);
    cp16(smaddr(&smB[0][row0 * 40 + q0 * 8]), Bg + row0 * DC + q0 * 8);
    cp16(smaddr(&smB[0][row1 * 40 + q1 * 8]), Bg + row1 * DC + q1 * 8);
    cp_commit(); cp_wait0(); __syncthreads();

    #pragma unroll 1
    for (int kt = 0; kt < DC / 32; ++kt) {
        const int cur = kt & 1, nxt = cur ^ 1;
        if (kt + 1 < DC / 32) {
            const int ko = (kt + 1) * 32;
            cp16(smaddr(&smA[nxt][row0 * 40 + q0 * 8]), Ag + row0 * DC + ko + q0 * 8);
            cp16(smaddr(&smA[nxt][row1 * 40 + q1 * 8]), Ag + row1 * DC + ko + q1 * 8);
            cp16(smaddr(&smB[nxt][row0 * 40 + q0 * 8]), Bg + row0 * DC + ko + q0 * 8);
            cp16(smaddr(&smB[nxt][row1 * 40 + q1 * 8]), Bg + row1 * DC + ko + q1 * 8);
            cp_commit();
        }
        #pragma unroll
        for (int c16 = 0; c16 < 2; ++c16) {
            unsigned int a[2][4];
            #pragma unroll
            for (int i = 0; i < 2; ++i) {
                int r   = wm * 32 + i * 16 + ((lane >> 3) & 1) * 8 + (lane & 7);
                int col = c16 * 16 + ((lane >> 4) & 1) * 8;
                ldmx4(a[i][0], a[i][1], a[i][2], a[i][3],
                      smaddr(&smA[cur][r * 40 + col]));
            }
            #pragma unroll
            for (int jg = 0; jg < 4; ++jg) {
                unsigned int b0, b1, b2, b3;
                int g  = lane >> 3;
                int rB = wn * 64 + jg * 16 + (g >> 1) * 8 + (lane & 7);
                int cB = c16 * 16 + (g & 1) * 8;
                ldmx4(b0, b1, b2, b3, smaddr(&smB[cur][rB * 40 + cB]));
                mma16816(acc[0][jg * 2],     a[0], b0, b1);
                mma16816(acc[1][jg * 2],     a[1], b0, b1);
                mma16816(acc[0][jg * 2 + 1], a[0], b2, b3);
                mma16816(acc[1][jg * 2 + 1], a[1], b2, b3);
            }
        }
        cp_wait0(); __syncthreads();
    }

    // ---- epilogue: per-token CTA min, smem candidate lists, write-out ----
    float e2v[8][2];
    #pragma unroll
    for (int j = 0; j < 8; ++j) {
        int n = nBase + wn * 64 + j * 8 + (lane & 3) * 2;
        e2v[j][0] = e2t[n]; e2v[j][1] = e2t[n + 1];
    }
    // min pass
    #pragma unroll
    for (int i = 0; i < 2; ++i) {
        #pragma unroll
        for (int h = 0; h < 2; ++h) {
            float mv = FLT_MAX;
            #pragma unroll
            for (int j = 0; j < 8; ++j) {
                mv = fminf(mv, fmaf(-2.f, acc[i][j][h * 2],     e2v[j][0]));
                mv = fminf(mv, fmaf(-2.f, acc[i][j][h * 2 + 1], e2v[j][1]));
            }
            mv = fminf(mv, __shfl_xor_sync(0xffffffffu, mv, 1));
            mv = fminf(mv, __shfl_xor_sync(0xffffffffu, mv, 2));
            if ((lane & 3) == 0) {
                int tokl = wm * 32 + i * 16 + h * 8 + (lane >> 2);
                sbest[wn][tokl] = mv;   // unique (wn, tokl) owner
            }
        }
    }
    __syncthreads();
    // insertion pass: s < ctamin + TAU -> smem list (cap 4), smem atomics only
    #pragma unroll
    for (int i = 0; i < 2; ++i) {
        #pragma unroll
        for (int h = 0; h < 2; ++h) {
            int tokl = wm * 32 + i * 16 + h * 8 + (lane >> 2);
            float thr = fminf(sbest[0][tokl], sbest[1][tokl]) + TAU;
            #pragma unroll
            for (int j = 0; j < 8; ++j) {
                #pragma unroll
                for (int c = 0; c < 2; ++c) {
                    float s = fmaf(-2.f, acc[i][j][h * 2 + c], e2v[j][c]);
                    if (s < thr) {
                        int bin = nBase + wn * 64 + j * 8 + (lane & 3) * 2 + c;
                        int p = atomicAdd(&scnt[tokl], 1);
                        if (p < 4) {
                            scand[tokl][p] =
                                ((unsigned int)__half_as_ushort(__float2half(s)) << 16)
                                | (unsigned int)bin;
                        }
                    }
                }
            }
        }
    }
    __syncthreads();
    // write-out: one record + one uint4 per token, coalesced
    if (tid < 128) {
        int tok = mBase + tid;
        uint2 rec;
        rec.x = __float_as_uint(fminf(sbest[0][tid], sbest[1][tid]));
        rec.y = (unsigned int)scnt[tid];
        g_part[(size_t)tok * 8 + nb] = rec;
        g_candl[(size_t)tok * 8 + nb] = *(uint4*)scand[tid];
    }
}

// ---------------------------------------------------------------------------
// RERANK: warp per token. gmin = min of 8 fp32 tile minima; filter stored
// candidates; 1 survivor -> done; else exact fp32 re-eval (validated recipe);
// overflow -> full exact scan. Then residual/r2/bf16/commit/idx update.
// ---------------------------------------------------------------------------
__global__ void __launch_bounds__(256) rerank_kernel(const float* __restrict__ cbt,
                                                     int t, float* __restrict__ idx_out)
{
    __shared__ float wsum[8];
    const int wid = threadIdx.x >> 5, lane = threadIdx.x & 31;
    const int tok = blockIdx.x * 8 + wid;
    const float* e2t = g_e2 + t * NBINS;
    const float* r = g_res + (size_t)tok * DC;

    float mnl = FLT_MAX; int cnt = 0;
    if (lane < 8) {
        uint2 pt = g_part[(size_t)tok * 8 + lane];
        mnl = __uint_as_float(pt.x);
        cnt = (int)pt.y;
    }
    float gmin = mnl;
    #pragma unroll
    for (int off = 16; off; off >>= 1)
        gmin = fminf(gmin, __shfl_xor_sync(0xffffffffu, gmin, off));
    const float thr = gmin + TAU;
    const bool ovf = __ballot_sync(0xffffffffu, lane < 8 && cnt > 4) != 0u;

    int besti;
    if (!ovf) {
        const int nb = lane >> 2, slot = lane & 3;
        const int cnb = __shfl_sync(0xffffffffu, cnt, nb);
        unsigned int pk = ((const unsigned int*)g_candl)[(size_t)tok * 32 + lane];
        bool valid = slot < cnb;
        float val = valid ? __half2float(__ushort_as_half((unsigned short)(pk >> 16)))
                          : FLT_MAX;
        int bin = (int)(pk & 0xFFFFu);
        bool surv = valid && (val <= thr);
        unsigned int mask = __ballot_sync(0xffffffffu, surv);
        if (__popc(mask) == 1) {
            besti = __shfl_sync(0xffffffffu, bin, __ffs(mask) - 1);
        } else {
            float bestv = FLT_MAX; besti = NBINS;
            const float r2tok = g_r2[tok];
            if (surv) {
                const float* e = cbt + (size_t)bin * DC;
                float acc = 0.f;
                #pragma unroll 8
                for (int k = 0; k < DC; ++k) acc = fmaf(r[k], e[k], acc);
                bestv = __fadd_rn(__fsub_rn(r2tok, __fmul_rn(2.f, acc)), e2t[bin]);
                besti = bin;
            }
            #pragma unroll
            for (int off = 16; off; off >>= 1) {
                float v = __shfl_xor_sync(0xffffffffu, bestv, off);
                int   i = __shfl_xor_sync(0xffffffffu, besti, off);
                if (v < bestv || (v == bestv && i < besti)) { bestv = v; besti = i; }
            }
        }
    } else {
        // overflow fallback: exact scan of all bins (validated recipe)
        float bestv = FLT_MAX; besti = NBINS;
        const float r2tok = g_r2[tok];
        for (int bin = lane; bin < NBINS; bin += 32) {
            const float* e = cbt + (size_t)bin * DC;
            float acc = 0.f;
            #pragma unroll 8
            for (int k = 0; k < DC; ++k) acc = fmaf(r[k], e[k], acc);
            float sc = __fadd_rn(__fsub_rn(r2tok, __fmul_rn(2.f, acc)), e2t[bin]);
            if (sc < bestv || (sc == bestv && bin < besti)) { bestv = sc; besti = bin; }
        }
        #pragma unroll
        for (int off = 16; off; off >>= 1) {
            float v = __shfl_xor_sync(0xffffffffu, bestv, off);
            int   i = __shfl_xor_sync(0xffffffffu, besti, off);
            if (v < bestv || (v == bestv && i < besti)) { bestv = v; besti = i; }
        }
    }

    // update residual (fp32 + bf16), next r2 (XLA order), commit, idx
    const float* e = cbt + (size_t)besti * DC;
    float* rw = g_res + (size_t)tok * DC;
    __nv_bfloat16* rw16 = g_res16 + (size_t)tok * DC;
    float s = 0.f;
    #pragma unroll
    for (int j = 0; j < 8; ++j) {
        int d = lane + j * 32;
        float rn_ = __fsub_rn(rw[d], e[d]);
        rw[d] = rn_;
        rw16[d] = __float2bfloat16(rn_);
        s = __fadd_rn(s, __fmul_rn(rn_, rn_));
    }
    #pragma unroll
    for (int off = 16; off; off >>= 1)
        s = __fadd_rn(s, __shfl_down_sync(0xffffffffu, s, off));
    if (lane == 0) {
        g_r2[tok] = s;
        wsum[wid] = s;
        idx_out[tok] = (float)besti;
    }
    __syncthreads();
    if (threadIdx.x == 0) {
        float acc = 0.f;
        #pragma unroll
        for (int w = 0; w < 8; ++w) acc += wsum[w];
        atomicAdd(&g_commit, acc);
    }
}

// ---------------------------------------------------------------------------
// OUT-PROJECTION, bf16x3 (round-11 passing): out = A'[.,768]*B'[512,768]^T + b
// ---------------------------------------------------------------------------
__global__ void __launch_bounds__(256) gemm_out_tc(const float* __restrict__ ob,
                                                   float* __restrict__ outp)
{
    __shared__ __align__(16) unsigned short smA[2][128 * 40];
    __shared__ __align__(16) unsigned short smB[2][128 * 40];
    const int tid   = threadIdx.x;
    const int mBase = blockIdx.y * 128;
    const int nBase = blockIdx.x * 128;
    const int wid = tid >> 5, lane = tid & 31;
    const int wm = wid & 3, wn = wid >> 2;

    const int c0 = tid * 2;
    const int row0 = c0 >> 2, q0 = c0 & 3;
    const int row1 = (c0 + 1) >> 2, q1 = (c0 + 1) & 3;
    const __nv_bfloat16* Ag = g_qs + (size_t)mBase * KS;
    const __nv_bfloat16* Bg = g_ws + (size_t)nBase * KS;

    float acc[2][8][4];
    #pragma unroll
    for (int i = 0; i < 2; ++i)
        #pragma unroll
        for (int j = 0; j < 8; ++j)
            #pragma unroll
            for (int k = 0; k < 4; ++k) acc[i][j][k] = 0.f;

    cp16(smaddr(&smA[0][row0 * 40 + q0 * 8]), Ag + (size_t)row0 * KS + q0 * 8);
    cp16(smaddr(&smA[0][row1 * 40 + q1 * 8]), Ag + (size_t)row1 * KS + q1 * 8);
    cp16(smaddr(&smB[0][row0 * 40 + q0 * 8]), Bg + (size_t)row0 * KS + q0 * 8);
    cp16(smaddr(&smB[0][row1 * 40 + q1 * 8]), Bg + (size_t)row1 * KS + q1 * 8);
    cp_commit(); cp_wait0(); __syncthreads();

    #pragma unroll 1
    for (int kt = 0; kt < KS / 32; ++kt) {
        const int cur = kt & 1, nxt = cur ^ 1;
        if (kt + 1 < KS / 32) {
            const int ko = (kt + 1) * 32;
            cp16(smaddr(&smA[nxt][row0 * 40 + q0 * 8]), Ag + (size_t)row0 * KS + ko + q0 * 8);
            cp16(smaddr(&smA[nxt][row1 * 40 + q1 * 8]), Ag + (size_t)row1 * KS + ko + q1 * 8);
            cp16(smaddr(&smB[nxt][row0 * 40 + q0 * 8]), Bg + (size_t)row0 * KS + ko + q0 * 8);
            cp16(smaddr(&smB[nxt][row1 * 40 + q1 * 8]), Bg + (size_t)row1 * KS + ko + q1 * 8);
            cp_commit();
        }
        #pragma unroll
        for (int c16 = 0; c16 < 2; ++c16) {
            unsigned int a[2][4];
            #pragma unroll
            for (int i = 0; i < 2; ++i) {
                int r   = wm * 32 + i * 16 + ((lane >> 3) & 1) * 8 + (lane & 7);
                int col = c16 * 16 + ((lane >> 4) & 1) * 8;
                ldmx4(a[i][0], a[i][1], a[i][2], a[i][3],
                      smaddr(&smA[cur][r * 40 + col]));
            }
            #pragma unroll
            for (int jg = 0; jg < 4; ++jg) {
                unsigned int b0, b1, b2, b3;
                int g  = lane >> 3;
                int rB = wn * 64 + jg * 16 + (g >> 1) * 8 + (lane & 7);
                int cB = c16 * 16 + (g & 1) * 8;
                ldmx4(b0, b1, b2, b3, smaddr(&smB[cur][rB * 40 + cB]));
                mma16816(acc[0][jg * 2],     a[0], b0, b1);
                mma16816(acc[1][jg * 2],     a[1], b0, b1);
                mma16816(acc[0][jg * 2 + 1], a[0], b2, b3);
                mma16816(acc[1][jg * 2 + 1], a[1], b2, b3);
            }
        }
        cp_wait0(); __syncthreads();
    }

    #pragma unroll
    for (int i = 0; i < 2; ++i) {
        #pragma unroll
        for (int j = 0; j < 8; ++j) {
            int n  = nBase + wn * 64 + j * 8 + (lane & 3) * 2;
            int m0 = mBase + wm * 32 + i * 16 + (lane >> 2);
            float b0v = ob[n], b1v = ob[n + 1];
            float2 lo = make_float2(acc[i][j][0] + b0v, acc[i][j][1] + b1v);
            float2 hi = make_float2(acc[i][j][2] + b0v, acc[i][j][3] + b1v);
            *(float2*)(outp + (size_t)m0 * DIN + n)       = lo;
            *(float2*)(outp + (size_t)(m0 + 8) * DIN + n) = hi;
        }
    }
}

// ---------------------------------------------------------------------------
// fp32 SIMT GEMM core (passing) for the in-projection (must stay bit-exact)
// ---------------------------------------------------------------------------
template<int KTOT>
__device__ __forceinline__ void mma128(const float* __restrict__ A,
                                       const float* __restrict__ B,
                                       int lda, int ldb,
                                       float (&acc)[8][8],
                                       float (*As)[16][132], float (*Bs)[16][132])
{
    const int tid = threadIdx.x;
    const int row = tid >> 1;
    const int kq  = (tid & 1) * 8;
    const int tx  = tid & 15;
    const int ty  = tid >> 4;
    const int NC = KTOT / 16;

    float4 pa0 = *(const float4*)(A + (size_t)row * lda + kq);
    float4 pa1 = *(const float4*)(A + (size_t)row * lda + kq + 4);
    float4 pb0 = *(const float4*)(B + (size_t)row * ldb + kq);
    float4 pb1 = *(const float4*)(B + (size_t)row * ldb + kq + 4);
    __syncthreads();
    As[0][kq + 0][row] = pa0.x; As[0][kq + 1][row] = pa0.y; As[0][kq + 2][row] = pa0.z; As[0][kq + 3][row] = pa0.w;
    As[0][kq + 4][row] = pa1.x; As[0][kq + 5][row] = pa1.y; As[0][kq + 6][row] = pa1.z; As[0][kq + 7][row] = pa1.w;
    Bs[0][kq + 0][row] = pb0.x; Bs[0][kq + 1][row] = pb0.y; Bs[0][kq + 2][row] = pb0.z; Bs[0][kq + 3][row] = pb0.w;
    Bs[0][kq + 4][row] = pb1.x; Bs[0][kq + 5][row] = pb1.y; Bs[0][kq + 6][row] = pb1.z; Bs[0][kq + 7][row] = pb1.w;
    __syncthreads();

    #pragma unroll 2
    for (int c = 0; c < NC; ++c) {
        const int cur = c & 1, nxt = cur ^ 1;
        if (c + 1 < NC) {
            const float* Ai = A + (size_t)row * lda + (c + 1) * 16 + kq;
            const float* Bi = B + (size_t)row * ldb + (c + 1) * 16 + kq;
            pa0 = *(const float4*)Ai;  pa1 = *(const float4*)(Ai + 4);
            pb0 = *(const float4*)Bi;  pb1 = *(const float4*)(Bi + 4);
        }
        #pragma unroll
        for (int k = 0; k < 16; ++k) {
            float4 a0 = *(const float4*)&As[cur][k][ty * 4];
            float4 a1 = *(const float4*)&As[cur][k][64 + ty * 4];
            float4 b0 = *(const float4*)&Bs[cur][k][tx * 4];
            float4 b1 = *(const float4*)&Bs[cur][k][64 + tx * 4];
            float ar[8] = {a0.x, a0.y, a0.z, a0.w, a1.x, a1.y, a1.z, a1.w};
            float br[8] = {b0.x, b0.y, b0.z, b0.w, b1.x, b1.y, b1.z, b1.w};
            #pragma unroll
            for (int i = 0; i < 8; ++i)
                #pragma unroll
                for (int j = 0; j < 8; ++j)
                    acc[i][j] = fmaf(ar[i], br[j], acc[i][j]);
        }
        if (c + 1 < NC) {
            As[nxt][kq + 0][row] = pa0.x; As[nxt][kq + 1][row] = pa0.y; As[nxt][kq + 2][row] = pa0.z; As[nxt][kq + 3][row] = pa0.w;
            As[nxt][kq + 4][row] = pa1.x; As[nxt][kq + 5][row] = pa1.y; As[nxt][kq + 6][row] = pa1.z; As[nxt][kq + 7][row] = pa1.w;
            Bs[nxt][kq + 0][row] = pb0.x; Bs[nxt][kq + 1][row] = pb0.y; Bs[nxt][kq + 2][row] = pb0.z; Bs[nxt][kq + 3][row] = pb0.w;
            Bs[nxt][kq + 4][row] = pb1.x; Bs[nxt][kq + 5][row] = pb1.y; Bs[nxt][kq + 6][row] = pb1.z; Bs[nxt][kq + 7][row] = pb1.w;
        }
        __syncthreads();
    }
}

__device__ __forceinline__ int map8(int base4, int i) {
    return (i < 4) ? base4 + i : 64 + base4 + (i - 4);
}

__global__ void __launch_bounds__(256, 2) gemm_in_kernel(const float* __restrict__ x,
                                                         const float* __restrict__ w,
                                                         const float* __restrict__ b)
{
    __shared__ __align__(16) float As[2][16][132];
    __shared__ __align__(16) float Bs[2][16][132];
    const int mBase = blockIdx.y * 128;
    const int nBase = blockIdx.x * 128;
    float acc[8][8] = {};
    mma128<DIN>(x + (size_t)mBase * DIN, w + (size_t)nBase * DIN, DIN, DIN, acc, As, Bs);
    const int tx = threadIdx.x & 15, ty = threadIdx.x >> 4;
    #pragma unroll
    for (int i = 0; i < 8; ++i) {
        int m = mBase + map8(ty * 4, i);
        #pragma unroll
        for (int j = 0; j < 8; ++j) {
            int n = nBase + map8(tx * 4, j);
            float v = tanh_ref(__fadd_rn(acc[i][j], b[n]));
            g_h  [(size_t)m * DC + n] = v;
            g_res[(size_t)m * DC + n] = v;
        }
    }
}

__global__ void fin_kernel(float* __restrict__ loss) {
    *loss = 0.1f * g_commit * (1.0f / 8388608.0f);
}

extern "C" void kernel_launch(void* const* d_in, const int* in_sizes, int n_in,
                              void* d_out, int out_size)
{
    const float* x     = (const float*)d_in[0];
    const float* in_w  = (const float*)d_in[1];
    const float* in_b  = (const float*)d_in[2];
    const float* out_w = (const float*)d_in[3];
    const float* out_b = (const float*)d_in[4];
    const float* cb    = (const float*)d_in[5];

    float* outp     = (float*)d_out;                       // [32768, 512]
    float* idx_out  = outp + (size_t)N_TOK * DIN;          // [8, 32768]
    float* loss_out = outp + (size_t)out_size - 1;         // scalar

    init_kernel<<<1, 1>>>();
    e2_kernel<<<(NQCB * NBINS * 32) / 256, 256>>>(cb);
    cb16_kernel<<<(NQCB * NBINS * DC / 4) / 256, 256>>>(cb);
    gemm_in_kernel<<<dim3(DC / 128, N_TOK / 128), 256>>>(x, in_w, in_b);
    prep_kernel<<<N_TOK / 8, 256>>>();
    for (int t = 0; t < NQCB; ++t) {
        screen_kernel<<<dim3(NBINS / 128, N_TOK / 128), 256>>>(t);
        rerank_kernel<<<N_TOK / 8, 256>>>(cb + (size_t)t * NBINS * DC, t,
                                          idx_out + (size_t)t * N_TOK);
    }
    wsplit_kernel<<<DIN, DC>>>(out_w);
    qsplit_kernel<<<(N_TOK * DC) / 256, 256>>>();
    gemm_out_tc<<<dim3(DIN / 128, N_TOK / 128), 256>>>(out_b, outp);
    fin_kernel<<<1, 1>>>(loss_out);
}

// round 15
// speedup vs baseline: 7.5716x; 7.5716x over previous
#include <cuda_runtime.h>
#include <cuda_bf16.h>
#include <cuda_fp16.h>
#include <math.h>
#include <float.h>

#define N_TOK 32768   // B*T
#define DC    256
#define DIN   512
#define NQCB  8
#define NBINS 1024
#define TAU   6.0f    // screen window (bf16 mma + fp16 value rounding budget)
#define KS    768     // split-K for bf16x3 out-projection

// -------- scratch (device globals: allocation-free) --------
__device__ float g_h[(size_t)N_TOK * DC];
__device__ float g_res[(size_t)N_TOK * DC];
__device__ __nv_bfloat16 g_res16[(size_t)N_TOK * DC];
__device__ __nv_bfloat16 g_cb16[(size_t)NQCB * NBINS * DC];
__device__ __half g_S[(size_t)N_TOK * NBINS];
__device__ __nv_bfloat16 g_qs[(size_t)N_TOK * KS];   // [qh | ql | qh]
__device__ __nv_bfloat16 g_ws[(size_t)DIN * KS];     // [wh | wh | wl]
__device__ float g_r2[N_TOK];
__device__ float g_e2[NQCB * NBINS];
__device__ float g_commit;

__global__ void init_kernel() { g_commit = 0.f; }

// XLA/Eigen float tanh rational approximation (matches reference bits)
__device__ __forceinline__ float tanh_ref(float x) {
    const float kClamp = 7.90531110763549805f;
    float xc = fminf(fmaxf(x, -kClamp), kClamp);
    const float a1  = 4.89352455891786e-03f, a3 = 6.37261928875436e-04f,
                a5  = 1.48572235717979e-05f, a7 = 5.12229709037114e-08f,
                a9  = -8.60467152213735e-11f, a11 = 2.00018790482477e-13f,
                a13 = -2.76076847742355e-16f;
    const float b0 = 4.89352518554385e-03f, b2 = 2.26843463243900e-03f,
                b4 = 1.18534705686654e-04f, b6 = 1.19825839466702e-06f;
    float x2 = __fmul_rn(xc, xc);
    float p = fmaf(x2, a13, a11);
    p = fmaf(x2, p, a9);  p = fmaf(x2, p, a7);
    p = fmaf(x2, p, a5);  p = fmaf(x2, p, a3);
    p = fmaf(x2, p, a1);  p = __fmul_rn(xc, p);
    float q = fmaf(x2, b6, b4);
    q = fmaf(x2, q, b2);  q = fmaf(x2, q, b0);
    float r = __fdiv_rn(p, q);
    return (fabsf(x) < 0.0004f) ? x : r;
}

// ||e||^2 per codebook row, XLA row-reduce order
__global__ void e2_kernel(const float* __restrict__ cb) {
    int gw   = (blockIdx.x * blockDim.x + threadIdx.x) >> 5;
    int lane = threadIdx.x & 31;
    if (gw >= NQCB * NBINS) return;
    const float* row = cb + (size_t)gw * DC;
    float s = 0.f;
    #pragma unroll
    for (int j = 0; j < DC / 32; ++j) {
        float v = row[lane + j * 32];
        s = __fadd_rn(s, __fmul_rn(v, v));
    }
    #pragma unroll
    for (int off = 16; off; off >>= 1)
        s = __fadd_rn(s, __shfl_down_sync(0xffffffffu, s, off));
    if (lane == 0) g_e2[gw] = s;
}

// codebooks fp32 -> bf16
__global__ void cb16_kernel(const float* __restrict__ cb) {
    size_t i = (size_t)blockIdx.x * blockDim.x + threadIdx.x;
    float4 v = ((const float4*)cb)[i];
    __nv_bfloat16 o[4];
    o[0] = __float2bfloat16(v.x); o[1] = __float2bfloat16(v.y);
    o[2] = __float2bfloat16(v.z); o[3] = __float2bfloat16(v.w);
    *(uint2*)(g_cb16 + i * 4) = *(uint2*)o;
}

// out_w split: [wh | wh | wl] rows of KS
__global__ void wsplit_kernel(const float* __restrict__ w) {
    int n = blockIdx.x, k = threadIdx.x;
    float v = w[(size_t)n * DC + k];
    __nv_bfloat16 hi = __float2bfloat16(v);
    __nv_bfloat16 lo = __float2bfloat16(__fsub_rn(v, __bfloat162float(hi)));
    g_ws[(size_t)n * KS + k]           = hi;
    g_ws[(size_t)n * KS + DC + k]      = hi;
    g_ws[(size_t)n * KS + 2 * DC + k]  = lo;
}

// quantized = h - res, split to [qh | ql | qh]
__global__ void qsplit_kernel() {
    int idx = blockIdx.x * blockDim.x + threadIdx.x;
    int m = idx >> 8, k = idx & 255;
    float q = __fsub_rn(g_h[(size_t)m * DC + k], g_res[(size_t)m * DC + k]);
    __nv_bfloat16 hi = __float2bfloat16(q);
    __nv_bfloat16 lo = __float2bfloat16(__fsub_rn(q, __bfloat162float(hi)));
    g_qs[(size_t)m * KS + k]          = hi;
    g_qs[(size_t)m * KS + DC + k]     = lo;
    g_qs[(size_t)m * KS + 2 * DC + k] = hi;
}

// after gemm_in: residual bf16 + r2 (one warp per token)
__global__ void prep_kernel() {
    const int wid = threadIdx.x >> 5, lane = threadIdx.x & 31;
    const int tok = blockIdx.x * 8 + wid;
    const float* r = g_res + (size_t)tok * DC;
    __nv_bfloat16* r16 = g_res16 + (size_t)tok * DC;
    float s = 0.f;
    #pragma unroll
    for (int j = 0; j < 8; ++j) {
        int d = lane + j * 32;
        float v = r[d];
        r16[d] = __float2bfloat16(v);
        s = __fadd_rn(s, __fmul_rn(v, v));
    }
    #pragma unroll
    for (int off = 16; off; off >>= 1)
        s = __fadd_rn(s, __shfl_down_sync(0xffffffffu, s, off));
    if (lane == 0) g_r2[tok] = s;
}

// ---------------- PTX helpers ----------------
__device__ __forceinline__ unsigned int smaddr(const void* p) {
    return (unsigned int)__cvta_generic_to_shared(p);
}
__device__ __forceinline__ void cp16(unsigned int dst, const void* src) {
    asm volatile("cp.async.cg.shared.global [%0], [%1], 16;\n" :: "r"(dst), "l"(src));
}
__device__ __forceinline__ void cp_commit() { asm volatile("cp.async.commit_group;\n"); }
__device__ __forceinline__ void cp_wait0()  { asm volatile("cp.async.wait_group 0;\n"); }
__device__ __forceinline__ void cp_wait1()  { asm volatile("cp.async.wait_group 1;\n"); }
__device__ __forceinline__ void ldmx4(unsigned int& r0, unsigned int& r1,
                                      unsigned int& r2, unsigned int& r3,
                                      unsigned int addr) {
    asm volatile("ldmatrix.sync.aligned.m8n8.x4.shared.b16 {%0,%1,%2,%3}, [%4];\n"
                 : "=r"(r0), "=r"(r1), "=r"(r2), "=r"(r3) : "r"(addr));
}
__device__ __forceinline__ void mma16816(float* d, const unsigned int* a,
                                         unsigned int b0, unsigned int b1) {
    asm volatile("mma.sync.aligned.m16n8k16.row.col.f32.bf16.bf16.f32 "
                 "{%0,%1,%2,%3}, {%4,%5,%6,%7}, {%8,%9}, {%0,%1,%2,%3};\n"
                 : "+f"(d[0]), "+f"(d[1]), "+f"(d[2]), "+f"(d[3])
                 : "r"(a[0]), "r"(a[1]), "r"(a[2]), "r"(a[3]), "r"(b0), "r"(b1));
}

// ---------------------------------------------------------------------------
// SCREEN: S[m][n] = e2[n] - 2*(bf16(r).bf16(e)), fp16 out. Round-11 GEMM body
// upgraded to a 3-STAGE cp.async pipeline: loads run two k-chunks ahead.
// Group audit (commit per chunk): prologue commits G0,G1; iter k commits
// G_{k+2} (k<6). At iter k<7 outstanding={G_k,G_{k+1}} -> wait_group 1 ensures
// G_k done; at k=7 outstanding={G7} -> wait_group 0.
// ---------------------------------------------------------------------------
__global__ void __launch_bounds__(256) screen_kernel(int t)
{
    extern __shared__ __align__(16) unsigned short sm3[];   // [3][A:5120|B:5120]
    const int tid   = threadIdx.x;
    const int mBase = blockIdx.y * 128;
    const int nBase = blockIdx.x * 128;
    const int wid = tid >> 5, lane = tid & 31;
    const int wm = wid & 3, wn = wid >> 2;

    const int c0 = tid * 2;
    const int row0 = c0 >> 2, q0 = c0 & 3;
    const int row1 = (c0 + 1) >> 2, q1 = (c0 + 1) & 3;
    const __nv_bfloat16* Ag = g_res16 + (size_t)mBase * DC;
    const __nv_bfloat16* Bg = g_cb16 + (size_t)t * NBINS * DC + (size_t)nBase * DC;
    const float* e2t = g_e2 + t * NBINS;

    float acc[2][8][4];
    #pragma unroll
    for (int i = 0; i < 2; ++i)
        #pragma unroll
        for (int j = 0; j < 8; ++j)
            #pragma unroll
            for (int k = 0; k < 4; ++k) acc[i][j][k] = 0.f;

    // prologue: chunks 0,1 -> stages 0,1 (one commit group each)
    #pragma unroll
    for (int p = 0; p < 2; ++p) {
        unsigned short* st = sm3 + p * 10240;
        const int ko = p * 32;
        cp16(smaddr(st + row0 * 40 + q0 * 8),        Ag + row0 * DC + ko + q0 * 8);
        cp16(smaddr(st + row1 * 40 + q1 * 8),        Ag + row1 * DC + ko + q1 * 8);
        cp16(smaddr(st + 5120 + row0 * 40 + q0 * 8), Bg + row0 * DC + ko + q0 * 8);
        cp16(smaddr(st + 5120 + row1 * 40 + q1 * 8), Bg + row1 * DC + ko + q1 * 8);
        cp_commit();
    }

    int stage = 0;
    #pragma unroll 1
    for (int kt = 0; kt < 8; ++kt) {
        if (kt < 7) cp_wait1(); else cp_wait0();
        __syncthreads();
        const unsigned short* As_ = sm3 + stage * 10240;
        const unsigned short* Bs_ = As_ + 5120;
        #pragma unroll
        for (int c16 = 0; c16 < 2; ++c16) {
            unsigned int a[2][4];
            #pragma unroll
            for (int i = 0; i < 2; ++i) {
                int r   = wm * 32 + i * 16 + ((lane >> 3) & 1) * 8 + (lane & 7);
                int col = c16 * 16 + ((lane >> 4) & 1) * 8;
                ldmx4(a[i][0], a[i][1], a[i][2], a[i][3],
                      smaddr(As_ + r * 40 + col));
            }
            #pragma unroll
            for (int jg = 0; jg < 4; ++jg) {
                unsigned int b0, b1, b2, b3;
                int g  = lane >> 3;
                int rB = wn * 64 + jg * 16 + (g >> 1) * 8 + (lane & 7);
                int cB = c16 * 16 + (g & 1) * 8;
                ldmx4(b0, b1, b2, b3, smaddr(Bs_ + rB * 40 + cB));
                mma16816(acc[0][jg * 2],     a[0], b0, b1);
                mma16816(acc[1][jg * 2],     a[1], b0, b1);
                mma16816(acc[0][jg * 2 + 1], a[0], b2, b3);
                mma16816(acc[1][jg * 2 + 1], a[1], b2, b3);
            }
        }
        if (kt + 2 < 8) {
            // issue chunk kt+2 into the stage just about to free up next iter
            unsigned short* st = sm3 + ((stage + 2) % 3) * 10240;
            const int ko = (kt + 2) * 32;
            cp16(smaddr(st + row0 * 40 + q0 * 8),        Ag + row0 * DC + ko + q0 * 8);
            cp16(smaddr(st + row1 * 40 + q1 * 8),        Ag + row1 * DC + ko + q1 * 8);
            cp16(smaddr(st + 5120 + row0 * 40 + q0 * 8), Bg + row0 * DC + ko + q0 * 8);
            cp16(smaddr(st + 5120 + row1 * 40 + q1 * 8), Bg + row1 * DC + ko + q1 * 8);
            cp_commit();
        }
        stage = (stage + 1) % 3;
        __syncthreads();   // all warps done with this stage before it is refilled
    }

    // epilogue: s = e2 - 2*dot, fp16 store (round-11 verbatim)
    #pragma unroll
    for (int i = 0; i < 2; ++i) {
        #pragma unroll
        for (int j = 0; j < 8; ++j) {
            int n  = nBase + wn * 64 + j * 8 + (lane & 3) * 2;
            int m0 = mBase + wm * 32 + i * 16 + (lane >> 2);
            float e0 = e2t[n], e1 = e2t[n + 1];
            __half2 lo = __floats2half2_rn(fmaf(-2.f, acc[i][j][0], e0),
                                           fmaf(-2.f, acc[i][j][1], e1));
            __half2 hi = __floats2half2_rn(fmaf(-2.f, acc[i][j][2], e0),
                                           fmaf(-2.f, acc[i][j][3], e1));
            *(__half2*)(g_S + (size_t)m0 * NBINS + n)       = lo;
            *(__half2*)(g_S + (size_t)(m0 + 8) * NBINS + n) = hi;
        }
    }
}

// ---------------------------------------------------------------------------
// RERANK (round-11 verbatim): warp per token over full S row.
// ---------------------------------------------------------------------------
__global__ void __launch_bounds__(256) rerank_kernel(const float* __restrict__ cbt,
                                                     int t, float* __restrict__ idx_out)
{
    __shared__ float wsum[8];
    const int wid = threadIdx.x >> 5, lane = threadIdx.x & 31;
    const int tok = blockIdx.x * 8 + wid;
    const __half* Srow = g_S + (size_t)tok * NBINS;
    const float* e2t = g_e2 + t * NBINS;

    int4 sv[4];
    #pragma unroll
    for (int j = 0; j < 4; ++j) sv[j] = ((const int4*)Srow)[j * 32 + lane];

    float mn = FLT_MAX;
    #pragma unroll
    for (int j = 0; j < 4; ++j) {
        const __half* h = (const __half*)&sv[j];
        #pragma unroll
        for (int i = 0; i < 8; ++i) mn = fminf(mn, __half2float(h[i]));
    }
    #pragma unroll
    for (int off = 16; off; off >>= 1)
        mn = fminf(mn, __shfl_xor_sync(0xffffffffu, mn, off));
    const float thr = mn + TAU;

    const float r2tok = g_r2[tok];
    const float* r = g_res + (size_t)tok * DC;
    float bestv = FLT_MAX; int besti = NBINS;
    #pragma unroll
    for (int j = 0; j < 4; ++j) {
        const __half* h = (const __half*)&sv[j];
        #pragma unroll
        for (int i = 0; i < 8; ++i) {
            if (__half2float(h[i]) <= thr) {
                int bin = j * 256 + lane * 8 + i;
                const float* e = cbt + (size_t)bin * DC;
                float acc = 0.f;
                #pragma unroll 8
                for (int k = 0; k < DC; ++k) acc = fmaf(r[k], e[k], acc);
                float sc = __fadd_rn(__fsub_rn(r2tok, __fmul_rn(2.f, acc)), e2t[bin]);
                if (sc < bestv || (sc == bestv && bin < besti)) { bestv = sc; besti = bin; }
            }
        }
    }
    #pragma unroll
    for (int off = 16; off; off >>= 1) {
        float v = __shfl_xor_sync(0xffffffffu, bestv, off);
        int   i = __shfl_xor_sync(0xffffffffu, besti, off);
        if (v < bestv || (v == bestv && i < besti)) { bestv = v; besti = i; }
    }

    const float* e = cbt + (size_t)besti * DC;
    float* rw = g_res + (size_t)tok * DC;
    __nv_bfloat16* rw16 = g_res16 + (size_t)tok * DC;
    float s = 0.f;
    #pragma unroll
    for (int j = 0; j < 8; ++j) {
        int d = lane + j * 32;
        float rn_ = __fsub_rn(rw[d], e[d]);
        rw[d] = rn_;
        rw16[d] = __float2bfloat16(rn_);
        s = __fadd_rn(s, __fmul_rn(rn_, rn_));
    }
    #pragma unroll
    for (int off = 16; off; off >>= 1)
        s = __fadd_rn(s, __shfl_down_sync(0xffffffffu, s, off));
    if (lane == 0) {
        g_r2[tok] = s;
        wsum[wid] = s;
        idx_out[tok] = (float)besti;
    }
    __syncthreads();
    if (threadIdx.x == 0) {
        float acc = 0.f;
        #pragma unroll
        for (int w = 0; w < 8; ++w) acc += wsum[w];
        atomicAdd(&g_commit, acc);
    }
}

// ---------------------------------------------------------------------------
// OUT-PROJECTION, bf16x3 (round-11 passing): out = A'[.,768]*B'[512,768]^T + b
// ---------------------------------------------------------------------------
__global__ void __launch_bounds__(256) gemm_out_tc(const float* __restrict__ ob,
                                                   float* __restrict__ outp)
{
    __shared__ __align__(16) unsigned short smA[2][128 * 40];
    __shared__ __align__(16) unsigned short smB[2][128 * 40];
    const int tid   = threadIdx.x;
    const int mBase = blockIdx.y * 128;
    const int nBase = blockIdx.x * 128;
    const int wid = tid >> 5, lane = tid & 31;
    const int wm = wid & 3, wn = wid >> 2;

    const int c0 = tid * 2;
    const int row0 = c0 >> 2, q0 = c0 & 3;
    const int row1 = (c0 + 1) >> 2, q1 = (c0 + 1) & 3;
    const __nv_bfloat16* Ag = g_qs + (size_t)mBase * KS;
    const __nv_bfloat16* Bg = g_ws + (size_t)nBase * KS;

    float acc[2][8][4];
    #pragma unroll
    for (int i = 0; i < 2; ++i)
        #pragma unroll
        for (int j = 0; j < 8; ++j)
            #pragma unroll
            for (int k = 0; k < 4; ++k) acc[i][j][k] = 0.f;

    cp16(smaddr(&smA[0][row0 * 40 + q0 * 8]), Ag + (size_t)row0 * KS + q0 * 8);
    cp16(smaddr(&smA[0][row1 * 40 + q1 * 8]), Ag + (size_t)row1 * KS + q1 * 8);
    cp16(smaddr(&smB[0][row0 * 40 + q0 * 8]), Bg + (size_t)row0 * KS + q0 * 8);
    cp16(smaddr(&smB[0][row1 * 40 + q1 * 8]), Bg + (size_t)row1 * KS + q1 * 8);
    cp_commit(); cp_wait0(); __syncthreads();

    #pragma unroll 1
    for (int kt = 0; kt < KS / 32; ++kt) {
        const int cur = kt & 1, nxt = cur ^ 1;
        if (kt + 1 < KS / 32) {
            const int ko = (kt + 1) * 32;
            cp16(smaddr(&smA[nxt][row0 * 40 + q0 * 8]), Ag + (size_t)row0 * KS + ko + q0 * 8);
            cp16(smaddr(&smA[nxt][row1 * 40 + q1 * 8]), Ag + (size_t)row1 * KS + ko + q1 * 8);
            cp16(smaddr(&smB[nxt][row0 * 40 + q0 * 8]), Bg + (size_t)row0 * KS + ko + q0 * 8);
            cp16(smaddr(&smB[nxt][row1 * 40 + q1 * 8]), Bg + (size_t)row1 * KS + ko + q1 * 8);
            cp_commit();
        }
        #pragma unroll
        for (int c16 = 0; c16 < 2; ++c16) {
            unsigned int a[2][4];
            #pragma unroll
            for (int i = 0; i < 2; ++i) {
                int r   = wm * 32 + i * 16 + ((lane >> 3) & 1) * 8 + (lane & 7);
                int col = c16 * 16 + ((lane >> 4) & 1) * 8;
                ldmx4(a[i][0], a[i][1], a[i][2], a[i][3],
                      smaddr(&smA[cur][r * 40 + col]));
            }
            #pragma unroll
            for (int jg = 0; jg < 4; ++jg) {
                unsigned int b0, b1, b2, b3;
                int g  = lane >> 3;
                int rB = wn * 64 + jg * 16 + (g >> 1) * 8 + (lane & 7);
                int cB = c16 * 16 + (g & 1) * 8;
                ldmx4(b0, b1, b2, b3, smaddr(&smB[cur][rB * 40 + cB]));
                mma16816(acc[0][jg * 2],     a[0], b0, b1);
                mma16816(acc[1][jg * 2],     a[1], b0, b1);
                mma16816(acc[0][jg * 2 + 1], a[0], b2, b3);
                mma16816(acc[1][jg * 2 + 1], a[1], b2, b3);
            }
        }
        cp_wait0(); __syncthreads();
    }

    #pragma unroll
    for (int i = 0; i < 2; ++i) {
        #pragma unroll
        for (int j = 0; j < 8; ++j) {
            int n  = nBase + wn * 64 + j * 8 + (lane & 3) * 2;
            int m0 = mBase + wm * 32 + i * 16 + (lane >> 2);
            float b0v = ob[n], b1v = ob[n + 1];
            float2 lo = make_float2(acc[i][j][0] + b0v, acc[i][j][1] + b1v);
            float2 hi = make_float2(acc[i][j][2] + b0v, acc[i][j][3] + b1v);
            *(float2*)(outp + (size_t)m0 * DIN + n)       = lo;
            *(float2*)(outp + (size_t)(m0 + 8) * DIN + n) = hi;
        }
    }
}

// ---------------------------------------------------------------------------
// fp32 SIMT GEMM core (passing) for the in-projection (must stay bit-exact)
// ---------------------------------------------------------------------------
template<int KTOT>
__device__ __forceinline__ void mma128(const float* __restrict__ A,
                                       const float* __restrict__ B,
                                       int lda, int ldb,
                                       float (&acc)[8][8],
                                       float (*As)[16][132], float (*Bs)[16][132])
{
    const int tid = threadIdx.x;
    const int row = tid >> 1;
    const int kq  = (tid & 1) * 8;
    const int tx  = tid & 15;
    const int ty  = tid >> 4;
    const int NC = KTOT / 16;

    float4 pa0 = *(const float4*)(A + (size_t)row * lda + kq);
    float4 pa1 = *(const float4*)(A + (size_t)row * lda + kq + 4);
    float4 pb0 = *(const float4*)(B + (size_t)row * ldb + kq);
    float4 pb1 = *(const float4*)(B + (size_t)row * ldb + kq + 4);
    __syncthreads();
    As[0][kq + 0][row] = pa0.x; As[0][kq + 1][row] = pa0.y; As[0][kq + 2][row] = pa0.z; As[0][kq + 3][row] = pa0.w;
    As[0][kq + 4][row] = pa1.x; As[0][kq + 5][row] = pa1.y; As[0][kq + 6][row] = pa1.z; As[0][kq + 7][row] = pa1.w;
    Bs[0][kq + 0][row] = pb0.x; Bs[0][kq + 1][row] = pb0.y; Bs[0][kq + 2][row] = pb0.z; Bs[0][kq + 3][row] = pb0.w;
    Bs[0][kq + 4][row] = pb1.x; Bs[0][kq + 5][row] = pb1.y; Bs[0][kq + 6][row] = pb1.z; Bs[0][kq + 7][row] = pb1.w;
    __syncthreads();

    #pragma unroll 2
    for (int c = 0; c < NC; ++c) {
        const int cur = c & 1, nxt = cur ^ 1;
        if (c + 1 < NC) {
            const float* Ai = A + (size_t)row * lda + (c + 1) * 16 + kq;
            const float* Bi = B + (size_t)row * ldb + (c + 1) * 16 + kq;
            pa0 = *(const float4*)Ai;  pa1 = *(const float4*)(Ai + 4);
            pb0 = *(const float4*)Bi;  pb1 = *(const float4*)(Bi + 4);
        }
        #pragma unroll
        for (int k = 0; k < 16; ++k) {
            float4 a0 = *(const float4*)&As[cur][k][ty * 4];
            float4 a1 = *(const float4*)&As[cur][k][64 + ty * 4];
            float4 b0 = *(const float4*)&Bs[cur][k][tx * 4];
            float4 b1 = *(const float4*)&Bs[cur][k][64 + tx * 4];
            float ar[8] = {a0.x, a0.y, a0.z, a0.w, a1.x, a1.y, a1.z, a1.w};
            float br[8] = {b0.x, b0.y, b0.z, b0.w, b1.x, b1.y, b1.z, b1.w};
            #pragma unroll
            for (int i = 0; i < 8; ++i)
                #pragma unroll
                for (int j = 0; j < 8; ++j)
                    acc[i][j] = fmaf(ar[i], br[j], acc[i][j]);
        }
        if (c + 1 < NC) {
            As[nxt][kq + 0][row] = pa0.x; As[nxt][kq + 1][row] = pa0.y; As[nxt][kq + 2][row] = pa0.z; As[nxt][kq + 3][row] = pa0.w;
            As[nxt][kq + 4][row] = pa1.x; As[nxt][kq + 5][row] = pa1.y; As[nxt][kq + 6][row] = pa1.z; As[nxt][kq + 7][row] = pa1.w;
            Bs[nxt][kq + 0][row] = pb0.x; Bs[nxt][kq + 1][row] = pb0.y; Bs[nxt][kq + 2][row] = pb0.z; Bs[nxt][kq + 3][row] = pb0.w;
            Bs[nxt][kq + 4][row] = pb1.x; Bs[nxt][kq + 5][row] = pb1.y; Bs[nxt][kq + 6][row] = pb1.z; Bs[nxt][kq + 7][row] = pb1.w;
        }
        __syncthreads();
    }
}

__device__ __forceinline__ int map8(int base4, int i) {
    return (i < 4) ? base4 + i : 64 + base4 + (i - 4);
}

__global__ void __launch_bounds__(256, 2) gemm_in_kernel(const float* __restrict__ x,
                                                         const float* __restrict__ w,
                                                         const float* __restrict__ b)
{
    __shared__ __align__(16) float As[2][16][132];
    __shared__ __align__(16) float Bs[2][16][132];
    const int mBase = blockIdx.y * 128;
    const int nBase = blockIdx.x * 128;
    float acc[8][8] = {};
    mma128<DIN>(x + (size_t)mBase * DIN, w + (size_t)nBase * DIN, DIN, DIN, acc, As, Bs);
    const int tx = threadIdx.x & 15, ty = threadIdx.x >> 4;
    #pragma unroll
    for (int i = 0; i < 8; ++i) {
        int m = mBase + map8(ty * 4, i);
        #pragma unroll
        for (int j = 0; j < 8; ++j) {
            int n = nBase + map8(tx * 4, j);
            float v = tanh_ref(__fadd_rn(acc[i][j], b[n]));
            g_h  [(size_t)m * DC + n] = v;
            g_res[(size_t)m * DC + n] = v;
        }
    }
}

__global__ void fin_kernel(float* __restrict__ loss) {
    *loss = 0.1f * g_commit * (1.0f / 8388608.0f);
}

extern "C" void kernel_launch(void* const* d_in, const int* in_sizes, int n_in,
                              void* d_out, int out_size)
{
    const float* x     = (const float*)d_in[0];
    const float* in_w  = (const float*)d_in[1];
    const float* in_b  = (const float*)d_in[2];
    const float* out_w = (const float*)d_in[3];
    const float* out_b = (const float*)d_in[4];
    const float* cb    = (const float*)d_in[5];

    float* outp     = (float*)d_out;                       // [32768, 512]
    float* idx_out  = outp + (size_t)N_TOK * DIN;          // [8, 32768]
    float* loss_out = outp + (size_t)out_size - 1;         // scalar

    cudaFuncSetAttribute(screen_kernel,
                         cudaFuncAttributeMaxDynamicSharedMemorySize, 61440);

    init_kernel<<<1, 1>>>();
    e2_kernel<<<(NQCB * NBINS * 32) / 256, 256>>>(cb);
    cb16_kernel<<<(NQCB * NBINS * DC / 4) / 256, 256>>>(cb);
    gemm_in_kernel<<<dim3(DC / 128, N_TOK / 128), 256>>>(x, in_w, in_b);
    prep_kernel<<<N_TOK / 8, 256>>>();
    for (int t = 0; t < NQCB; ++t) {
        screen_kernel<<<dim3(NBINS / 128, N_TOK / 128), 256, 61440>>>(t);
        rerank_kernel<<<N_TOK / 8, 256>>>(cb + (size_t)t * NBINS * DC, t,
                                          idx_out + (size_t)t * N_TOK);
    }
    wsplit_kernel<<<DIN, DC>>>(out_w);
    qsplit_kernel<<<(N_TOK * DC) / 256, 256>>>();
    gemm_out_tc<<<dim3(DIN / 128, N_TOK / 128), 256>>>(out_b, outp);
    fin_kernel<<<1, 1>>>(loss_out);
}